// round 4
// baseline (speedup 1.0000x reference)
#include <cuda_runtime.h>

#define N_L   8192
#define N_H   32768
#define FDIM  128
#define KSEL  32
#define BLOCK 128

// Packed source points: (x, y, z, x^2+y^2+z^2). 128KB static device scratch (allowed).
__device__ float4 g_posl4[N_L];

__global__ void pack_kernel(const float* __restrict__ pos_l) {
    int i = blockIdx.x * blockDim.x + threadIdx.x;
    if (i < N_L) {
        float x = pos_l[3 * i + 0];
        float y = pos_l[3 * i + 1];
        float z = pos_l[3 * i + 2];
        g_posl4[i] = make_float4(x, y, z, fmaf(x, x, fmaf(y, y, z * z)));
    }
}

// s = l^2 - 2 h.l  =  d2 - h^2   (h^2 is constant per target, so ordering is preserved)
__device__ __forceinline__ float cand_s(float hx, float hy, float hz, float4 p) {
    float dot = fmaf(hx, p.x, fmaf(hy, p.y, hz * p.z));
    return fmaf(-2.0f, dot, p.w);
}

// Insert s into ascending sorted 32-register list, dropping the old max.
// Pure FMNMX bubble: 2 instructions per stage, fully unrolled, stays in registers.
__device__ __forceinline__ void insert32(float (&q)[KSEL], float s) {
    float cur = s;
#pragma unroll
    for (int j = 0; j < KSEL; j++) {
        float lo = fminf(q[j], cur);
        cur = fmaxf(q[j], cur);
        q[j] = lo;
    }
}

__global__ __launch_bounds__(BLOCK) void knn_interp_kernel(
    const float* __restrict__ x,
    const float* __restrict__ pos_h,
    float* __restrict__ out)
{
    __shared__ int   s_idx[BLOCK * KSEL];
    __shared__ float s_w[BLOCK * KSEL];
    __shared__ float s_wsum[BLOCK];

    const int t   = threadIdx.x;
    const int tgt = blockIdx.x * BLOCK + t;

    const float hx = pos_h[3 * tgt + 0];
    const float hy = pos_h[3 * tgt + 1];
    const float hz = pos_h[3 * tgt + 2];
    const float h2 = fmaf(hx, hx, fmaf(hy, hy, hz * hz));

    float q[KSEL];
#pragma unroll
    for (int j = 0; j < KSEL; j++) q[j] = __int_as_float(0x7f800000);  // +inf

    // ---- Pass 1: top-32 smallest s-values (values only) ----
#pragma unroll 1
    for (int i = 0; i < N_L; i += 4) {
        float4 p0 = g_posl4[i + 0];
        float4 p1 = g_posl4[i + 1];
        float4 p2 = g_posl4[i + 2];
        float4 p3 = g_posl4[i + 3];
        float s0 = cand_s(hx, hy, hz, p0);
        float s1 = cand_s(hx, hy, hz, p1);
        float s2 = cand_s(hx, hy, hz, p2);
        float s3 = cand_s(hx, hy, hz, p3);
        if (s0 < q[KSEL - 1]) insert32(q, s0);
        if (s1 < q[KSEL - 1]) insert32(q, s1);
        if (s2 < q[KSEL - 1]) insert32(q, s2);
        if (s3 < q[KSEL - 1]) insert32(q, s3);
    }
    const float T = q[KSEL - 1];  // 32nd smallest s

    // ---- Pass 2: recompute (bit-identical fmaf sequence), compact idx + weights ----
    int   cnt  = 0;
    float wsum = 0.0f;
    const int base = t * KSEL;
#pragma unroll 1
    for (int i = 0; i < N_L; i += 4) {
        float4 p0 = g_posl4[i + 0];
        float4 p1 = g_posl4[i + 1];
        float4 p2 = g_posl4[i + 2];
        float4 p3 = g_posl4[i + 3];
        float s0 = cand_s(hx, hy, hz, p0);
        float s1 = cand_s(hx, hy, hz, p1);
        float s2 = cand_s(hx, hy, hz, p2);
        float s3 = cand_s(hx, hy, hz, p3);
#pragma unroll
        for (int u = 0; u < 4; u++) {
            float su = (u == 0) ? s0 : (u == 1) ? s1 : (u == 2) ? s2 : s3;
            if (su <= T && cnt < KSEL) {
                float d2 = su + h2;
                float w  = 1.0f / fmaxf(d2, 1e-16f);
                s_idx[base + cnt] = i + u;
                s_w[base + cnt]   = w;
                wsum += w;
                cnt++;
            }
        }
    }
    // Paranoia pad (count >= 32 is guaranteed absent fp ties weirdness)
    while (cnt < KSEL) { s_idx[base + cnt] = 0; s_w[base + cnt] = 0.0f; cnt++; }
    s_wsum[t] = wsum;
    __syncthreads();

    // ---- Phase 3: warp-cooperative gather + weighted reduce ----
    // Each warp handles 32 local targets; lane l owns float4 column l of the 128-f row.
    const int lane = t & 31;
    const int wid  = t >> 5;
    const float4* __restrict__ x4   = (const float4*)x;
    float4* __restrict__       out4 = (float4*)out;

    for (int lt = wid * 32; lt < wid * 32 + 32; ++lt) {
        float4 acc = make_float4(0.f, 0.f, 0.f, 0.f);
        const int b = lt * KSEL;
#pragma unroll 4
        for (int k = 0; k < KSEL; k++) {
            int   id = s_idx[b + k];
            float wg = s_w[b + k];
            float4 v = __ldg(&x4[id * (FDIM / 4) + lane]);
            acc.x = fmaf(wg, v.x, acc.x);
            acc.y = fmaf(wg, v.y, acc.y);
            acc.z = fmaf(wg, v.z, acc.z);
            acc.w = fmaf(wg, v.w, acc.w);
        }
        float inv = 1.0f / s_wsum[lt];
        int g = blockIdx.x * BLOCK + lt;
        out4[g * (FDIM / 4) + lane] =
            make_float4(acc.x * inv, acc.y * inv, acc.z * inv, acc.w * inv);
    }
}

extern "C" void kernel_launch(void* const* d_in, const int* in_sizes, int n_in,
                              void* d_out, int out_size) {
    const float* x     = (const float*)d_in[0];
    const float* pos_l = (const float*)d_in[1];
    const float* pos_h = (const float*)d_in[2];
    float* out = (float*)d_out;

    pack_kernel<<<(N_L + 255) / 256, 256>>>(pos_l);
    knn_interp_kernel<<<N_H / BLOCK, BLOCK>>>(x, pos_h, out);
}

// round 7
// speedup vs baseline: 1.9339x; 1.9339x over previous
#include <cuda_runtime.h>

#define N_L    8192
#define N_H    32768
#define FDIM   128
#define KSEL   32
#define NBINS  4096        // 16^3 Morton cells
#define TPB    32          // targets per block
#define SPLIT  2
#define THREADS (TPB * SPLIT)   // 64
#define RANGE  (N_L / SPLIT)    // 4096

// Static device scratch (allocation-free).
__device__ float4 g_posl4[N_L];
__device__ int    g_hist[NBINS];
__device__ int    g_cursor[NBINS];
__device__ int    g_bin[N_H];
__device__ int    g_order[N_H];

__global__ void pack_kernel(const float* __restrict__ pos_l) {
    int i = blockIdx.x * blockDim.x + threadIdx.x;
    if (i < N_L) {
        float x = pos_l[3 * i + 0];
        float y = pos_l[3 * i + 1];
        float z = pos_l[3 * i + 2];
        g_posl4[i] = make_float4(x, y, z, fmaf(x, x, fmaf(y, y, z * z)));
    }
}

__global__ void zero_hist_kernel() {
    int i = blockIdx.x * blockDim.x + threadIdx.x;
    if (i < NBINS) g_hist[i] = 0;
}

__device__ __forceinline__ int spread4(int b) {
    return (b & 1) | ((b & 2) << 2) | ((b & 4) << 4) | ((b & 8) << 6);
}

__global__ void bin_kernel(const float* __restrict__ pos_h) {
    int i = blockIdx.x * blockDim.x + threadIdx.x;
    if (i < N_H) {
        float x = pos_h[3 * i + 0];
        float y = pos_h[3 * i + 1];
        float z = pos_h[3 * i + 2];
        int cx = min(max((int)((x + 5.0f) * 1.6f), 0), 15);
        int cy = min(max((int)((y + 5.0f) * 1.6f), 0), 15);
        int cz = min(max((int)((z + 5.0f) * 1.6f), 0), 15);
        int m = spread4(cx) | (spread4(cy) << 1) | (spread4(cz) << 2);
        g_bin[i] = m;
        atomicAdd(&g_hist[m], 1);
    }
}

// Single block, 1024 threads: exclusive prefix over 4096 bins -> cursors.
__global__ void prefix_kernel() {
    __shared__ int s_part[1024];
    int t = threadIdx.x;
    int base = t * 4;
    int loc[4];
    int sum = 0;
#pragma unroll
    for (int j = 0; j < 4; j++) { loc[j] = sum; sum += g_hist[base + j]; }
    s_part[t] = sum;
    __syncthreads();
    for (int d = 1; d < 1024; d <<= 1) {
        int add = (t >= d) ? s_part[t - d] : 0;
        __syncthreads();
        s_part[t] += add;
        __syncthreads();
    }
    int excl = (t == 0) ? 0 : s_part[t - 1];
#pragma unroll
    for (int j = 0; j < 4; j++) g_cursor[base + j] = excl + loc[j];
}

__global__ void scatter_kernel() {
    int i = blockIdx.x * blockDim.x + threadIdx.x;
    if (i < N_H) {
        int b = g_bin[i];
        int p = atomicAdd(&g_cursor[b], 1);
        g_order[p] = i;
    }
}

// s = l^2 - 2 h.l  (d2 minus constant h^2 -> same ordering)
__device__ __forceinline__ float cand_s(float hx, float hy, float hz, float4 p) {
    float dot = fmaf(hx, p.x, fmaf(hy, p.y, hz * p.z));
    return fmaf(-2.0f, dot, p.w);
}

// Ascending sorted 32-register list, drop old max. Pure FMNMX bubble.
__device__ __forceinline__ void insert32(float (&q)[KSEL], float s) {
    float cur = s;
#pragma unroll
    for (int j = 0; j < KSEL; j++) {
        float lo = fminf(q[j], cur);
        cur = fmaxf(q[j], cur);
        q[j] = lo;
    }
}

__global__ __launch_bounds__(THREADS) void knn_interp_kernel(
    const float* __restrict__ x,
    const float* __restrict__ pos_h,
    float* __restrict__ out)
{
    __shared__ float s_q1[TPB * KSEL];               // split-1 pass-1 values
    __shared__ int   s_i0[TPB * KSEL], s_i1[TPB * KSEL];
    __shared__ float s_w0[TPB * KSEL], s_w1[TPB * KSEL];
    __shared__ float s_T[TPB];
    __shared__ int   s_c0[TPB];
    __shared__ int   s_orig[TPB];
    __shared__ float s_wsum[TPB];

    const int t  = threadIdx.x;
    const int tl = t & (TPB - 1);      // target-local
    const int sp = t >> 5;             // split (== warp id)
    const int orig = g_order[blockIdx.x * TPB + tl];
    if (sp == 0) s_orig[tl] = orig;

    const float hx = pos_h[3 * orig + 0];
    const float hy = pos_h[3 * orig + 1];
    const float hz = pos_h[3 * orig + 2];
    const float h2 = fmaf(hx, hx, fmaf(hy, hy, hz * hz));

    float q[KSEL];
#pragma unroll
    for (int j = 0; j < KSEL; j++) q[j] = __int_as_float(0x7f800000);

    const int i0 = sp * RANGE;

    // ---- Pass 1: per-split top-32 values over own half of pos_l ----
#pragma unroll 1
    for (int i = i0; i < i0 + RANGE; i += 4) {
        float4 p0 = __ldg(&g_posl4[i + 0]);
        float4 p1 = __ldg(&g_posl4[i + 1]);
        float4 p2 = __ldg(&g_posl4[i + 2]);
        float4 p3 = __ldg(&g_posl4[i + 3]);
        float s0 = cand_s(hx, hy, hz, p0);
        float s1 = cand_s(hx, hy, hz, p1);
        float s2 = cand_s(hx, hy, hz, p2);
        float s3 = cand_s(hx, hy, hz, p3);
        float m = fminf(fminf(s0, s1), fminf(s2, s3));
        if (m < q[KSEL - 1]) {
            if (s0 < q[KSEL - 1]) insert32(q, s0);
            if (s1 < q[KSEL - 1]) insert32(q, s1);
            if (s2 < q[KSEL - 1]) insert32(q, s2);
            if (s3 < q[KSEL - 1]) insert32(q, s3);
        }
    }

    if (sp == 1) {
#pragma unroll
        for (int j = 0; j < KSEL; j++) s_q1[tl * KSEL + j] = q[j];
    }
    __syncthreads();

    // ---- Exact merge (split-0 thread): 32nd smallest of the 64-value union ----
    if (sp == 0) {
#pragma unroll 1
        for (int j = 0; j < KSEL; j++) {
            float v = s_q1[tl * KSEL + j];
            if (v < q[KSEL - 1]) insert32(q, v);
            else break;                       // s_q1 ascending, q[31] nonincreasing
        }
        s_T[tl] = q[KSEL - 1];
    }
    __syncthreads();

    // ---- Pass 2: recompute (bit-identical fmaf) and compact idx+weight ----
    const float T = s_T[tl];
    int cnt = 0;
    int*   ridx = sp ? s_i1 : s_i0;
    float* rw   = sp ? s_w1 : s_w0;
    const int rb = tl * KSEL;
#pragma unroll 1
    for (int i = i0; i < i0 + RANGE; i += 4) {
        float4 p0 = __ldg(&g_posl4[i + 0]);
        float4 p1 = __ldg(&g_posl4[i + 1]);
        float4 p2 = __ldg(&g_posl4[i + 2]);
        float4 p3 = __ldg(&g_posl4[i + 3]);
        float s0 = cand_s(hx, hy, hz, p0);
        float s1 = cand_s(hx, hy, hz, p1);
        float s2 = cand_s(hx, hy, hz, p2);
        float s3 = cand_s(hx, hy, hz, p3);
        float m = fminf(fminf(s0, s1), fminf(s2, s3));
        if (m <= T) {
            if (s0 <= T && cnt < KSEL) { ridx[rb + cnt] = i + 0; rw[rb + cnt] = 1.0f / fmaxf(s0 + h2, 1e-16f); cnt++; }
            if (s1 <= T && cnt < KSEL) { ridx[rb + cnt] = i + 1; rw[rb + cnt] = 1.0f / fmaxf(s1 + h2, 1e-16f); cnt++; }
            if (s2 <= T && cnt < KSEL) { ridx[rb + cnt] = i + 2; rw[rb + cnt] = 1.0f / fmaxf(s2 + h2, 1e-16f); cnt++; }
            if (s3 <= T && cnt < KSEL) { ridx[rb + cnt] = i + 3; rw[rb + cnt] = 1.0f / fmaxf(s3 + h2, 1e-16f); cnt++; }
        }
    }
    if (sp == 0) s_c0[tl] = cnt;
    __syncthreads();

    // ---- Deterministic weight sum (split-0 region first, then split-1) ----
    if (sp == 0) {
        int c0 = cnt;
        float ws = 0.0f;
#pragma unroll 1
        for (int k = 0; k < KSEL; k++)
            ws += (k < c0) ? s_w0[rb + k] : s_w1[rb + k - c0];
        s_wsum[tl] = ws;
    }
    __syncthreads();

    // ---- Phase 3: warp-cooperative gather + weighted reduce ----
    const int lane = t & 31;
    const float4* __restrict__ x4   = (const float4*)x;
    float4* __restrict__       out4 = (float4*)out;

    for (int lt = sp * (TPB / 2); lt < sp * (TPB / 2) + (TPB / 2); ++lt) {
        const int c0 = s_c0[lt];
        const int b  = lt * KSEL;
        float4 acc = make_float4(0.f, 0.f, 0.f, 0.f);
#pragma unroll 4
        for (int k = 0; k < KSEL; k++) {
            int   id = (k < c0) ? s_i0[b + k] : s_i1[b + k - c0];
            float wg = (k < c0) ? s_w0[b + k] : s_w1[b + k - c0];
            float4 v = __ldg(&x4[id * (FDIM / 4) + lane]);
            acc.x = fmaf(wg, v.x, acc.x);
            acc.y = fmaf(wg, v.y, acc.y);
            acc.z = fmaf(wg, v.z, acc.z);
            acc.w = fmaf(wg, v.w, acc.w);
        }
        float inv = 1.0f / s_wsum[lt];
        int o = s_orig[lt];
        out4[o * (FDIM / 4) + lane] =
            make_float4(acc.x * inv, acc.y * inv, acc.z * inv, acc.w * inv);
    }
}

extern "C" void kernel_launch(void* const* d_in, const int* in_sizes, int n_in,
                              void* d_out, int out_size) {
    const float* x     = (const float*)d_in[0];
    const float* pos_l = (const float*)d_in[1];
    const float* pos_h = (const float*)d_in[2];
    float* out = (float*)d_out;

    pack_kernel<<<(N_L + 255) / 256, 256>>>(pos_l);
    zero_hist_kernel<<<(NBINS + 255) / 256, 256>>>();
    bin_kernel<<<(N_H + 255) / 256, 256>>>(pos_h);
    prefix_kernel<<<1, 1024>>>();
    scatter_kernel<<<(N_H + 255) / 256, 256>>>();
    knn_interp_kernel<<<N_H / TPB, THREADS>>>(x, pos_h, out);
}